// round 2
// baseline (speedup 1.0000x reference)
#include <cuda_runtime.h>
#include <cuda_bf16.h>
#include <math.h>

// Problem constants
#define BB 16
#define LL 50
#define PP 49
#define TT 20
#define DD 512
#define HH 8
#define DH 64
#define DFF 2048
#define BL (BB*LL)              // 800
#define NROW_IMG (BL*TT)        // 16000
#define NROW_TIT (BL*PP)        // 39200
#define NEGV (-1000000000.0f)
#define LN_EPS 1e-6f

// ---------------------------------------------------------------------------
// Scratch (device globals; no allocation allowed)
// ---------------------------------------------------------------------------
__device__ float g_hid_img [(size_t)NROW_IMG * DD];   // attention out (pre-proj)
__device__ float g_hid_tit [(size_t)NROW_TIT * DD];
__device__ float g_hidp_img[(size_t)NROW_IMG * DD];   // post-proj (residual + ffn input)
__device__ float g_hidp_tit[(size_t)NROW_TIT * DD];
__device__ float g_ffh_img [(size_t)NROW_IMG * DFF];  // gelu(x@w1^T+b1)
__device__ float g_ffh_tit [(size_t)NROW_TIT * DFF];
__device__ float g_ff2_img [(size_t)NROW_IMG * DD];   // ffn output (pre-LN)
__device__ float g_ff2_tit [(size_t)NROW_TIT * DD];

// ---------------------------------------------------------------------------
// Fused attention kernel: one block per (b*L+l, h).
// Computes raw scores, both scaled/masked softmaxes, and both PV products.
// ---------------------------------------------------------------------------
__global__ void __launch_bounds__(256) attn_kernel(
    const float* __restrict__ img,      // (B,L,P,D)
    const float* __restrict__ title,    // (B,L,T,D)
    const int*   __restrict__ mask,     // (B,L,T)
    const float* __restrict__ s_img,    // (H,P)
    const float* __restrict__ s_tit)    // (H,T)
{
    int blk = blockIdx.x;             // 0 .. BL*H-1
    int h   = blk % HH;
    int bl  = blk / HH;

    const float* imgp = img   + (size_t)bl * PP * DD + h * DH;  // [p][d], row stride DD
    const float* titp = title + (size_t)bl * TT * DD + h * DH;  // [t][d]
    const int*   mp   = mask  + (size_t)bl * TT;

    __shared__ float sI[PP * DH];    // 49*64
    __shared__ float sT[TT * DH];    // 20*64
    __shared__ float sRaw[PP * TT];  // [p][t]
    __shared__ float sPi [PP * TT];  // p_img [p][t]
    __shared__ float sPt [TT * PP];  // p_tit [t][p]
    __shared__ int   sM[TT];

    int tid = threadIdx.x;
    for (int i = tid; i < PP * DH; i += 256) {
        int p = i >> 6, d = i & 63;
        sI[i] = imgp[(size_t)p * DD + d];
    }
    for (int i = tid; i < TT * DH; i += 256) {
        int t = i >> 6, d = i & 63;
        sT[i] = titp[(size_t)t * DD + d];
    }
    if (tid < TT) sM[tid] = mp[tid];
    __syncthreads();

    // raw[p][t] = <img_p, tit_t> / 8
    for (int i = tid; i < PP * TT; i += 256) {
        int p = i / TT, t = i % TT;
        const float* ip = &sI[p * DH];
        const float* tp = &sT[t * DH];
        float acc = 0.f;
        #pragma unroll
        for (int d = 0; d < DH; d++) acc += ip[d] * tp[d];
        sRaw[i] = acc * 0.125f;
    }
    __syncthreads();

    // softmax over t for each p (p_img), scale by s_img[h,p], mask over t
    if (tid < PP) {
        int p = tid;
        float sc = s_img[h * PP + p];
        float mx = -1e30f;
        for (int t = 0; t < TT; t++) {
            float x = (sM[t] == 0) ? NEGV : sRaw[p * TT + t] * sc;
            sPi[p * TT + t] = x;
            mx = fmaxf(mx, x);
        }
        float sum = 0.f;
        for (int t = 0; t < TT; t++) {
            float e = expf(sPi[p * TT + t] - mx);
            sPi[p * TT + t] = e;
            sum += e;
        }
        float inv = 1.f / sum;
        for (int t = 0; t < TT; t++) sPi[p * TT + t] *= inv;
    }
    // softmax over p for each t (p_tit), scale by s_tit[h,t], full-row mask on t
    if (tid >= 64 && tid < 64 + TT) {
        int t = tid - 64;
        float sc = s_tit[h * TT + t];
        bool m0 = (sM[t] == 0);
        float mx = -1e30f;
        for (int p = 0; p < PP; p++) {
            float x = m0 ? NEGV : sRaw[p * TT + t] * sc;
            sPt[t * PP + p] = x;
            mx = fmaxf(mx, x);
        }
        float sum = 0.f;
        for (int p = 0; p < PP; p++) {
            float e = expf(sPt[t * PP + p] - mx);
            sPt[t * PP + p] = e;
            sum += e;
        }
        float inv = 1.f / sum;
        for (int p = 0; p < PP; p++) sPt[t * PP + p] *= inv;
    }
    __syncthreads();

    // hid_tit[p][d] = sum_t p_img[p][t] * tit[t][d]
    for (int i = tid; i < PP * DH; i += 256) {
        int p = i >> 6, d = i & 63;
        float acc = 0.f;
        #pragma unroll
        for (int t = 0; t < TT; t++) acc += sPi[p * TT + t] * sT[t * DH + d];
        g_hid_tit[((size_t)bl * PP + p) * DD + h * DH + d] = acc;
    }
    // hid_img[t][d] = sum_p p_tit[t][p] * img[p][d]
    for (int i = tid; i < TT * DH; i += 256) {
        int t = i >> 6, d = i & 63;
        float acc = 0.f;
        #pragma unroll
        for (int p = 0; p < PP; p++) acc += sPt[t * PP + p] * sI[p * DH + d];
        g_hid_img[((size_t)bl * TT + t) * DD + h * DH + d] = acc;
    }
}

// ---------------------------------------------------------------------------
// SGEMM: C[M,N] = act(A[M,K] @ W[N,K]^T + bias[N]).  128x128x16 tile,
// 256 threads, 8x8 micro-tile.  act: 0 = none, 1 = gelu(tanh).
// N and K are multiples of 128/16; M may be ragged.
// ---------------------------------------------------------------------------
__device__ __forceinline__ float gelu_tanh_f(float x) {
    float x3 = x * x * x;
    return 0.5f * x * (1.f + tanhf(0.7978845608028654f * (x + 0.044715f * x3)));
}

#define GBM 128
#define GBN 128
#define GBK 16

__global__ void __launch_bounds__(256) gemm_bias_act(
    const float* __restrict__ A, const float* __restrict__ W,
    const float* __restrict__ bias, float* __restrict__ C,
    int M, int N, int K, int act)
{
    __shared__ float As[GBK][GBM];
    __shared__ float Ws[GBK][GBN];

    int tid = threadIdx.x;
    int tx = tid & 15, ty = tid >> 4;
    int m0 = blockIdx.y * GBM;
    int n0 = blockIdx.x * GBN;

    float acc[8][8];
    #pragma unroll
    for (int i = 0; i < 8; i++)
        #pragma unroll
        for (int j = 0; j < 8; j++) acc[i][j] = 0.f;

    for (int k0 = 0; k0 < K; k0 += GBK) {
        // A tile: 128 rows x 16 k  (512 float4 loads, 2 per thread)
        #pragma unroll
        for (int l = 0; l < 2; l++) {
            int id = tid + l * 256;
            int row = id >> 2, kq = id & 3;
            float4 v = make_float4(0.f, 0.f, 0.f, 0.f);
            int gr = m0 + row;
            if (gr < M) v = *(const float4*)&A[(size_t)gr * K + k0 + kq * 4];
            As[kq * 4 + 0][row] = v.x;
            As[kq * 4 + 1][row] = v.y;
            As[kq * 4 + 2][row] = v.z;
            As[kq * 4 + 3][row] = v.w;
        }
        // W tile (N is always a multiple of 128 -> no guard)
        #pragma unroll
        for (int l = 0; l < 2; l++) {
            int id = tid + l * 256;
            int row = id >> 2, kq = id & 3;
            float4 v = *(const float4*)&W[(size_t)(n0 + row) * K + k0 + kq * 4];
            Ws[kq * 4 + 0][row] = v.x;
            Ws[kq * 4 + 1][row] = v.y;
            Ws[kq * 4 + 2][row] = v.z;
            Ws[kq * 4 + 3][row] = v.w;
        }
        __syncthreads();

        #pragma unroll
        for (int kk = 0; kk < GBK; kk++) {
            float a[8], b[8];
            *(float4*)&a[0] = *(const float4*)&As[kk][ty * 8 + 0];
            *(float4*)&a[4] = *(const float4*)&As[kk][ty * 8 + 4];
            *(float4*)&b[0] = *(const float4*)&Ws[kk][tx * 8 + 0];
            *(float4*)&b[4] = *(const float4*)&Ws[kk][tx * 8 + 4];
            #pragma unroll
            for (int i = 0; i < 8; i++)
                #pragma unroll
                for (int j = 0; j < 8; j++) acc[i][j] += a[i] * b[j];
        }
        __syncthreads();
    }

    float bv[8];
    *(float4*)&bv[0] = *(const float4*)&bias[n0 + tx * 8 + 0];
    *(float4*)&bv[4] = *(const float4*)&bias[n0 + tx * 8 + 4];

    #pragma unroll
    for (int i = 0; i < 8; i++) {
        int m = m0 + ty * 8 + i;
        if (m < M) {
            float o[8];
            #pragma unroll
            for (int j = 0; j < 8; j++) {
                float v = acc[i][j] + bv[j];
                o[j] = act ? gelu_tanh_f(v) : v;
            }
            float* cp = &C[(size_t)m * N + n0 + tx * 8];
            *(float4*)&cp[0] = *(float4*)&o[0];
            *(float4*)&cp[4] = *(float4*)&o[4];
        }
    }
}

// ---------------------------------------------------------------------------
// out = R + a * (Y - mean) / (std + eps) + b   per row of 512, ddof=1
// ---------------------------------------------------------------------------
__global__ void __launch_bounds__(128) ln_res_kernel(
    const float* __restrict__ Y, const float* __restrict__ R,
    const float* __restrict__ ga, const float* __restrict__ gb,
    float* __restrict__ O)
{
    __shared__ float sbuf[4];
    int row = blockIdx.x;
    size_t base = (size_t)row * DD;
    int tid = threadIdx.x;

    float x[4];
    #pragma unroll
    for (int i = 0; i < 4; i++) x[i] = Y[base + tid + i * 128];

    float s = x[0] + x[1] + x[2] + x[3];
    #pragma unroll
    for (int o = 16; o > 0; o >>= 1) s += __shfl_xor_sync(0xffffffffu, s, o);
    if ((tid & 31) == 0) sbuf[tid >> 5] = s;
    __syncthreads();
    float mean = (sbuf[0] + sbuf[1] + sbuf[2] + sbuf[3]) * (1.f / 512.f);
    __syncthreads();

    float q = 0.f;
    #pragma unroll
    for (int i = 0; i < 4; i++) { float d = x[i] - mean; q += d * d; }
    #pragma unroll
    for (int o = 16; o > 0; o >>= 1) q += __shfl_xor_sync(0xffffffffu, q, o);
    if ((tid & 31) == 0) sbuf[tid >> 5] = q;
    __syncthreads();
    float var = (sbuf[0] + sbuf[1] + sbuf[2] + sbuf[3]) * (1.f / 511.f);
    float inv = 1.f / (sqrtf(var) + LN_EPS);

    #pragma unroll
    for (int i = 0; i < 4; i++) {
        int n = tid + i * 128;
        O[base + n] = R[base + n] + ga[n] * (x[i] - mean) * inv + gb[n];
    }
}

// ---------------------------------------------------------------------------
extern "C" void kernel_launch(void* const* d_in, const int* in_sizes, int n_in,
                              void* d_out, int out_size)
{
    const float* img         = (const float*)d_in[0];
    const float* title       = (const float*)d_in[1];
    const int*   mask        = (const int*)  d_in[2];
    const float* scale_img   = (const float*)d_in[3];
    const float* scale_title = (const float*)d_in[4];
    const float* w_proj      = (const float*)d_in[5];
    const float* b_proj      = (const float*)d_in[6];
    const float* w1_img      = (const float*)d_in[7];
    const float* b1_img      = (const float*)d_in[8];
    const float* w2_img      = (const float*)d_in[9];
    const float* b2_img      = (const float*)d_in[10];
    const float* w1_tit      = (const float*)d_in[11];
    const float* b1_tit      = (const float*)d_in[12];
    const float* w2_tit      = (const float*)d_in[13];
    const float* b2_tit      = (const float*)d_in[14];
    const float* ln_a_img    = (const float*)d_in[15];
    const float* ln_b_img    = (const float*)d_in[16];
    const float* ln_a_tit    = (const float*)d_in[17];
    const float* ln_b_tit    = (const float*)d_in[18];

    float* out_img = (float*)d_out;
    float* out_tit = out_img + (size_t)NROW_IMG * DD;

    float *hid_img, *hid_tit, *hidp_img, *hidp_tit, *ffh_img, *ffh_tit, *ff2_img, *ff2_tit;
    cudaGetSymbolAddress((void**)&hid_img,  g_hid_img);
    cudaGetSymbolAddress((void**)&hid_tit,  g_hid_tit);
    cudaGetSymbolAddress((void**)&hidp_img, g_hidp_img);
    cudaGetSymbolAddress((void**)&hidp_tit, g_hidp_tit);
    cudaGetSymbolAddress((void**)&ffh_img,  g_ffh_img);
    cudaGetSymbolAddress((void**)&ffh_tit,  g_ffh_tit);
    cudaGetSymbolAddress((void**)&ff2_img,  g_ff2_img);
    cudaGetSymbolAddress((void**)&ff2_tit,  g_ff2_tit);

    // 1. attention
    attn_kernel<<<BL * HH, 256>>>(img, title, mask, scale_img, scale_title);

    // 2. shared projection
    {
        dim3 g(DD / GBN, (NROW_IMG + GBM - 1) / GBM);
        gemm_bias_act<<<g, 256>>>(hid_img, w_proj, b_proj, hidp_img, NROW_IMG, DD, DD, 0);
    }
    {
        dim3 g(DD / GBN, (NROW_TIT + GBM - 1) / GBM);
        gemm_bias_act<<<g, 256>>>(hid_tit, w_proj, b_proj, hidp_tit, NROW_TIT, DD, DD, 0);
    }

    // 3. FFN layer 1 (gelu)
    {
        dim3 g(DFF / GBN, (NROW_IMG + GBM - 1) / GBM);
        gemm_bias_act<<<g, 256>>>(hidp_img, w1_img, b1_img, ffh_img, NROW_IMG, DFF, DD, 1);
    }
    {
        dim3 g(DFF / GBN, (NROW_TIT + GBM - 1) / GBM);
        gemm_bias_act<<<g, 256>>>(hidp_tit, w1_tit, b1_tit, ffh_tit, NROW_TIT, DFF, DD, 1);
    }

    // 4. FFN layer 2
    {
        dim3 g(DD / GBN, (NROW_IMG + GBM - 1) / GBM);
        gemm_bias_act<<<g, 256>>>(ffh_img, w2_img, b2_img, ff2_img, NROW_IMG, DD, DFF, 0);
    }
    {
        dim3 g(DD / GBN, (NROW_TIT + GBM - 1) / GBM);
        gemm_bias_act<<<g, 256>>>(ffh_tit, w2_tit, b2_tit, ff2_tit, NROW_TIT, DD, DFF, 0);
    }

    // 5. LayerNorm + residual
    ln_res_kernel<<<NROW_IMG, 128>>>(ff2_img, hidp_img, ln_a_img, ln_b_img, out_img);
    ln_res_kernel<<<NROW_TIT, 128>>>(ff2_tit, hidp_tit, ln_a_tit, ln_b_tit, out_tit);
}

// round 5
// speedup vs baseline: 1.8672x; 1.8672x over previous
#include <cuda_runtime.h>
#include <cuda_bf16.h>
#include <math.h>
#include <stdint.h>

// Problem constants
#define BB 16
#define LL 50
#define PP 49
#define TT 20
#define DD 512
#define HH 8
#define DH 64
#define DFF 2048
#define BL (BB*LL)              // 800
#define NROW_IMG (BL*TT)        // 16000
#define NROW_TIT (BL*PP)        // 39200
#define NEGV (-1000000000.0f)
#define LN_EPS 1e-6f

// ---------------------------------------------------------------------------
// Scratch (device globals)
// ---------------------------------------------------------------------------
__device__ __align__(16) __nv_bfloat16 g_hid_img_h[(size_t)NROW_IMG * DD];
__device__ __align__(16) __nv_bfloat16 g_hid_img_l[(size_t)NROW_IMG * DD];
__device__ __align__(16) __nv_bfloat16 g_hid_tit_h[(size_t)NROW_TIT * DD];
__device__ __align__(16) __nv_bfloat16 g_hid_tit_l[(size_t)NROW_TIT * DD];
__device__ __align__(16) float         g_hidp_img  [(size_t)NROW_IMG * DD];
__device__ __align__(16) float         g_hidp_tit  [(size_t)NROW_TIT * DD];
__device__ __align__(16) __nv_bfloat16 g_hidp_img_h[(size_t)NROW_IMG * DD];
__device__ __align__(16) __nv_bfloat16 g_hidp_img_l[(size_t)NROW_IMG * DD];
__device__ __align__(16) __nv_bfloat16 g_hidp_tit_h[(size_t)NROW_TIT * DD];
__device__ __align__(16) __nv_bfloat16 g_hidp_tit_l[(size_t)NROW_TIT * DD];
__device__ __align__(16) __nv_bfloat16 g_ffh_img_h[(size_t)NROW_IMG * DFF];
__device__ __align__(16) __nv_bfloat16 g_ffh_img_l[(size_t)NROW_IMG * DFF];
__device__ __align__(16) __nv_bfloat16 g_ffh_tit_h[(size_t)NROW_TIT * DFF];
__device__ __align__(16) __nv_bfloat16 g_ffh_tit_l[(size_t)NROW_TIT * DFF];
__device__ __align__(16) float g_ff2_img[(size_t)NROW_IMG * DD];
__device__ __align__(16) float g_ff2_tit[(size_t)NROW_TIT * DD];
__device__ __align__(16) __nv_bfloat16 g_wp_h [(size_t)DD * DD];
__device__ __align__(16) __nv_bfloat16 g_wp_l [(size_t)DD * DD];
__device__ __align__(16) __nv_bfloat16 g_w1i_h[(size_t)DFF * DD];
__device__ __align__(16) __nv_bfloat16 g_w1i_l[(size_t)DFF * DD];
__device__ __align__(16) __nv_bfloat16 g_w1t_h[(size_t)DFF * DD];
__device__ __align__(16) __nv_bfloat16 g_w1t_l[(size_t)DFF * DD];
__device__ __align__(16) __nv_bfloat16 g_w2i_h[(size_t)DD * DFF];
__device__ __align__(16) __nv_bfloat16 g_w2i_l[(size_t)DD * DFF];
__device__ __align__(16) __nv_bfloat16 g_w2t_h[(size_t)DD * DFF];
__device__ __align__(16) __nv_bfloat16 g_w2t_l[(size_t)DD * DFF];

// ---------------------------------------------------------------------------
// Helpers
// ---------------------------------------------------------------------------
__device__ __forceinline__ uint32_t smem_u32(const void* p) {
    uint32_t a;
    asm("{ .reg .u64 t; cvta.to.shared.u64 t, %1; cvt.u32.u64 %0, t; }" : "=r"(a) : "l"(p));
    return a;
}
__device__ __forceinline__ void cp16(uint32_t dst, const void* src, int sz) {
    asm volatile("cp.async.cg.shared.global [%0], [%1], 16, %2;"
                 :: "r"(dst), "l"(src), "r"(sz));
}
__device__ __forceinline__ void cp_commit() { asm volatile("cp.async.commit_group;" ::: "memory"); }
__device__ __forceinline__ void cp_wait1()  { asm volatile("cp.async.wait_group 1;" ::: "memory"); }
__device__ __forceinline__ void cp_wait0()  { asm volatile("cp.async.wait_group 0;" ::: "memory"); }

__device__ __forceinline__ void ldsm4(uint32_t* r, uint32_t addr) {
    asm volatile("ldmatrix.sync.aligned.m8n8.x4.shared.b16 {%0,%1,%2,%3}, [%4];"
                 : "=r"(r[0]), "=r"(r[1]), "=r"(r[2]), "=r"(r[3]) : "r"(addr));
}
__device__ __forceinline__ void mma16816(float* c, const uint32_t* a, const uint32_t* b) {
    asm volatile(
        "mma.sync.aligned.m16n8k16.row.col.f32.bf16.bf16.f32 "
        "{%0,%1,%2,%3}, {%4,%5,%6,%7}, {%8,%9}, {%0,%1,%2,%3};"
        : "+f"(c[0]), "+f"(c[1]), "+f"(c[2]), "+f"(c[3])
        : "r"(a[0]), "r"(a[1]), "r"(a[2]), "r"(a[3]), "r"(b[0]), "r"(b[1]));
}

__device__ __forceinline__ float gelu_tanh_f(float x) {
    float x3 = x * x * x;
    return 0.5f * x * (1.f + tanhf(0.7978845608028654f * (x + 0.044715f * x3)));
}
__device__ __forceinline__ void split_f32(float v, __nv_bfloat16& h, __nv_bfloat16& l) {
    h = __float2bfloat16(v);
    l = __float2bfloat16(v - __bfloat162float(h));
}

// ---------------------------------------------------------------------------
// Weight split kernel
// ---------------------------------------------------------------------------
__global__ void __launch_bounds__(256) split_kernel(
    const float* __restrict__ x, __nv_bfloat16* __restrict__ hi,
    __nv_bfloat16* __restrict__ lo, int n)
{
    int i = (blockIdx.x * 256 + threadIdx.x) * 4;
    if (i >= n) return;
    float4 v = *(const float4*)(x + i);
    __nv_bfloat16 h0, h1, h2, h3, l0, l1, l2, l3;
    split_f32(v.x, h0, l0); split_f32(v.y, h1, l1);
    split_f32(v.z, h2, l2); split_f32(v.w, h3, l3);
    __nv_bfloat162 hp0 = __halves2bfloat162(h0, h1);
    __nv_bfloat162 hp1 = __halves2bfloat162(h2, h3);
    __nv_bfloat162 lp0 = __halves2bfloat162(l0, l1);
    __nv_bfloat162 lp1 = __halves2bfloat162(l2, l3);
    *(uint2*)(hi + i) = make_uint2(*(uint32_t*)&hp0, *(uint32_t*)&hp1);
    *(uint2*)(lo + i) = make_uint2(*(uint32_t*)&lp0, *(uint32_t*)&lp1);
}

// ---------------------------------------------------------------------------
// Fused attention (unchanged from R2 baseline, emits bf16 hi/lo)
// ---------------------------------------------------------------------------
__global__ void __launch_bounds__(256) attn_kernel(
    const float* __restrict__ img, const float* __restrict__ title,
    const int* __restrict__ mask,
    const float* __restrict__ s_img, const float* __restrict__ s_tit)
{
    int blk = blockIdx.x;
    int h   = blk % HH;
    int bl  = blk / HH;

    const float* imgp = img   + (size_t)bl * PP * DD + h * DH;
    const float* titp = title + (size_t)bl * TT * DD + h * DH;
    const int*   mp   = mask  + (size_t)bl * TT;

    __shared__ float sI[PP * DH];
    __shared__ float sT[TT * DH];
    __shared__ float sRaw[PP * TT];
    __shared__ float sPi [PP * TT];
    __shared__ float sPt [TT * PP];
    __shared__ int   sM[TT];

    int tid = threadIdx.x;
    for (int i = tid; i < PP * DH; i += 256) {
        int p = i >> 6, d = i & 63;
        sI[i] = imgp[(size_t)p * DD + d];
    }
    for (int i = tid; i < TT * DH; i += 256) {
        int t = i >> 6, d = i & 63;
        sT[i] = titp[(size_t)t * DD + d];
    }
    if (tid < TT) sM[tid] = mp[tid];
    __syncthreads();

    for (int i = tid; i < PP * TT; i += 256) {
        int p = i / TT, t = i % TT;
        const float* ip = &sI[p * DH];
        const float* tp = &sT[t * DH];
        float acc = 0.f;
        #pragma unroll
        for (int d = 0; d < DH; d++) acc += ip[d] * tp[d];
        sRaw[i] = acc * 0.125f;
    }
    __syncthreads();

    if (tid < PP) {
        int p = tid;
        float sc = s_img[h * PP + p];
        float mx = -1e30f;
        for (int t = 0; t < TT; t++) {
            float x = (sM[t] == 0) ? NEGV : sRaw[p * TT + t] * sc;
            sPi[p * TT + t] = x;
            mx = fmaxf(mx, x);
        }
        float sum = 0.f;
        for (int t = 0; t < TT; t++) {
            float e = expf(sPi[p * TT + t] - mx);
            sPi[p * TT + t] = e;
            sum += e;
        }
        float inv = 1.f / sum;
        for (int t = 0; t < TT; t++) sPi[p * TT + t] *= inv;
    }
    if (tid >= 64 && tid < 64 + TT) {
        int t = tid - 64;
        float sc = s_tit[h * TT + t];
        bool m0 = (sM[t] == 0);
        float mx = -1e30f;
        for (int p = 0; p < PP; p++) {
            float x = m0 ? NEGV : sRaw[p * TT + t] * sc;
            sPt[t * PP + p] = x;
            mx = fmaxf(mx, x);
        }
        float sum = 0.f;
        for (int p = 0; p < PP; p++) {
            float e = expf(sPt[t * PP + p] - mx);
            sPt[t * PP + p] = e;
            sum += e;
        }
        float inv = 1.f / sum;
        for (int p = 0; p < PP; p++) sPt[t * PP + p] *= inv;
    }
    __syncthreads();

    for (int i = tid; i < PP * DH; i += 256) {
        int p = i >> 6, d = i & 63;
        float acc = 0.f;
        #pragma unroll
        for (int t = 0; t < TT; t++) acc += sPi[p * TT + t] * sT[t * DH + d];
        size_t idx = ((size_t)bl * PP + p) * DD + h * DH + d;
        __nv_bfloat16 hh, ll;
        split_f32(acc, hh, ll);
        g_hid_tit_h[idx] = hh;
        g_hid_tit_l[idx] = ll;
    }
    for (int i = tid; i < TT * DH; i += 256) {
        int t = i >> 6, d = i & 63;
        float acc = 0.f;
        #pragma unroll
        for (int p = 0; p < PP; p++) acc += sPt[t * PP + p] * sI[p * DH + d];
        size_t idx = ((size_t)bl * TT + t) * DD + h * DH + d;
        __nv_bfloat16 hh, ll;
        split_f32(acc, hh, ll);
        g_hid_img_h[idx] = hh;
        g_hid_img_l[idx] = ll;
    }
}

// ---------------------------------------------------------------------------
// mma.sync GEMM (bf16x3): C[M,N] = act(A @ W^T + bias)
// Block tile 128x128, 8 warps (warp tile 32m x 64n), KC=32, double-buffered.
// SMEM per stage: Ah, Al, Wh, Wl each [128][32] bf16 padded to stride 40.
// ---------------------------------------------------------------------------
#define KC 32
#define PSTRIDE 40                       // padded row stride in elements
#define TEN_BYTES (128 * PSTRIDE * 2)    // 10240 bytes per tensor
#define STG_BYTES (4 * TEN_BYTES)        // 40960 per stage
#define SMEM_GEMM (2 * STG_BYTES)        // 81920

__device__ __forceinline__ void load_stage(
    uint32_t st,
    const __nv_bfloat16* __restrict__ Ah, const __nv_bfloat16* __restrict__ Al,
    const __nv_bfloat16* __restrict__ Wh, const __nv_bfloat16* __restrict__ Wl,
    int m0, int n0, int M, int K, int k0, int tid)
{
    #pragma unroll
    for (int i = 0; i < 2; i++) {
        int c = tid + i * 256;            // 0..511
        int row = c >> 2, kseg = c & 3;   // row<128, 16B segment
        uint32_t doff = (uint32_t)(row * (PSTRIDE * 2) + kseg * 16);
        int ar = m0 + row;
        int ok = (ar < M);
        size_t ao = (size_t)(ok ? ar : 0) * K + k0 + kseg * 8;
        cp16(st + doff,                 Ah + ao, ok ? 16 : 0);
        cp16(st + TEN_BYTES + doff,     Al + ao, ok ? 16 : 0);
        size_t wo = (size_t)(n0 + row) * K + k0 + kseg * 8;
        cp16(st + 2 * TEN_BYTES + doff, Wh + wo, 16);
        cp16(st + 3 * TEN_BYTES + doff, Wl + wo, 16);
    }
}

__global__ void __launch_bounds__(256) gemm_mma(
    const __nv_bfloat16* __restrict__ Ah, const __nv_bfloat16* __restrict__ Al,
    const __nv_bfloat16* __restrict__ Wh, const __nv_bfloat16* __restrict__ Wl,
    const float* __restrict__ bias,
    float* __restrict__ Cf, __nv_bfloat16* __restrict__ Chi, __nv_bfloat16* __restrict__ Clo,
    int M, int N, int K, int act)
{
    extern __shared__ __align__(16) char smem[];
    uint32_t sb = smem_u32(smem);
    int tid  = threadIdx.x;
    int wid  = tid >> 5, lane = tid & 31;
    int m0   = blockIdx.y * 128;
    int n0   = blockIdx.x * 128;
    int wm   = (wid & 3) * 32;            // warp m offset in tile
    int wn   = (wid >> 2) * 64;           // warp n offset in tile

    float acc[2][8][4];
    #pragma unroll
    for (int a = 0; a < 2; a++)
        #pragma unroll
        for (int b = 0; b < 8; b++)
            #pragma unroll
            for (int c = 0; c < 4; c++) acc[a][b][c] = 0.f;

    int nk = K / KC;
    load_stage(sb, Ah, Al, Wh, Wl, m0, n0, M, K, 0, tid);
    cp_commit();
    load_stage(sb + STG_BYTES, Ah, Al, Wh, Wl, m0, n0, M, K, KC, tid);
    cp_commit();

    // per-lane fragment address components (element offsets within stage tensors)
    uint32_t a_row = (uint32_t)(lane & 15);          // row within 16-row tile
    uint32_t a_kof = (uint32_t)((lane >> 4) << 3);   // 0 or 8
    uint32_t b_r8  = (uint32_t)(lane & 7);
    uint32_t b_kof = (uint32_t)(((lane >> 3) & 1) << 3);
    uint32_t b_pr  = (uint32_t)(lane >> 4);          // which nt of pair

    for (int it = 0; it < nk; it++) {
        if (it < nk - 1) cp_wait1(); else cp_wait0();
        __syncthreads();
        uint32_t st = sb + (uint32_t)(it & 1) * STG_BYTES;

        #pragma unroll
        for (int kk = 0; kk < KC; kk += 16) {
            uint32_t ah[2][4], al[2][4], bh[8][2], blr[8][2];
            #pragma unroll
            for (int mt = 0; mt < 2; mt++) {
                uint32_t r = (uint32_t)(wm + mt * 16) + a_row;
                uint32_t ad = st + r * (PSTRIDE * 2) + ((uint32_t)kk + a_kof) * 2;
                ldsm4(ah[mt], ad);
                ldsm4(al[mt], ad + TEN_BYTES);
            }
            #pragma unroll
            for (int np = 0; np < 4; np++) {
                uint32_t rr = (uint32_t)wn + ((uint32_t)np * 2 + b_pr) * 8 + b_r8;
                uint32_t bd = st + 2 * TEN_BYTES + rr * (PSTRIDE * 2) + ((uint32_t)kk + b_kof) * 2;
                uint32_t t0[4], t1[4];
                ldsm4(t0, bd);
                ldsm4(t1, bd + TEN_BYTES);
                bh [np*2][0] = t0[0]; bh [np*2][1] = t0[1];
                bh [np*2+1][0] = t0[2]; bh [np*2+1][1] = t0[3];
                blr[np*2][0] = t1[0]; blr[np*2][1] = t1[1];
                blr[np*2+1][0] = t1[2]; blr[np*2+1][1] = t1[3];
            }
            #pragma unroll
            for (int mt = 0; mt < 2; mt++)
                #pragma unroll
                for (int nt = 0; nt < 8; nt++) {
                    mma16816(acc[mt][nt], ah[mt], bh[nt]);
                    mma16816(acc[mt][nt], ah[mt], blr[nt]);
                    mma16816(acc[mt][nt], al[mt], bh[nt]);
                }
        }
        __syncthreads();
        if (it + 2 < nk) {
            load_stage(st, Ah, Al, Wh, Wl, m0, n0, M, K, (it + 2) * KC, tid);
            cp_commit();
        }
    }

    // epilogue
    int gr = lane >> 2;
    int gc = (lane & 3) * 2;
    #pragma unroll
    for (int mt = 0; mt < 2; mt++) {
        int m_lo = m0 + wm + mt * 16 + gr;
        int m_hi = m_lo + 8;
        #pragma unroll
        for (int nt = 0; nt < 8; nt++) {
            int n = n0 + wn + nt * 8 + gc;
            float2 bv = *(const float2*)&bias[n];
            float v0 = acc[mt][nt][0] + bv.x;
            float v1 = acc[mt][nt][1] + bv.y;
            float v2 = acc[mt][nt][2] + bv.x;
            float v3 = acc[mt][nt][3] + bv.y;
            if (act) { v0 = gelu_tanh_f(v0); v1 = gelu_tanh_f(v1);
                       v2 = gelu_tanh_f(v2); v3 = gelu_tanh_f(v3); }
            if (m_lo < M) {
                size_t o = (size_t)m_lo * N + n;
                if (Cf) *(float2*)&Cf[o] = make_float2(v0, v1);
                if (Chi) {
                    __nv_bfloat16 h0, l0, h1, l1;
                    split_f32(v0, h0, l0); split_f32(v1, h1, l1);
                    __nv_bfloat162 hp = __halves2bfloat162(h0, h1);
                    __nv_bfloat162 lp = __halves2bfloat162(l0, l1);
                    *(uint32_t*)&Chi[o] = *(uint32_t*)&hp;
                    *(uint32_t*)&Clo[o] = *(uint32_t*)&lp;
                }
            }
            if (m_hi < M) {
                size_t o = (size_t)m_hi * N + n;
                if (Cf) *(float2*)&Cf[o] = make_float2(v2, v3);
                if (Chi) {
                    __nv_bfloat16 h0, l0, h1, l1;
                    split_f32(v2, h0, l0); split_f32(v3, h1, l1);
                    __nv_bfloat162 hp = __halves2bfloat162(h0, h1);
                    __nv_bfloat162 lp = __halves2bfloat162(l0, l1);
                    *(uint32_t*)&Chi[o] = *(uint32_t*)&hp;
                    *(uint32_t*)&Clo[o] = *(uint32_t*)&lp;
                }
            }
        }
    }
}

// ---------------------------------------------------------------------------
// out = R + a * (Y - mean) / (std + eps) + b   per row of 512, ddof=1
// ---------------------------------------------------------------------------
__global__ void __launch_bounds__(128) ln_res_kernel(
    const float* __restrict__ Y, const float* __restrict__ R,
    const float* __restrict__ ga, const float* __restrict__ gb,
    float* __restrict__ O)
{
    __shared__ float sbuf[4];
    int row = blockIdx.x;
    size_t base = (size_t)row * DD;
    int tid = threadIdx.x;

    float x[4];
    #pragma unroll
    for (int i = 0; i < 4; i++) x[i] = Y[base + tid + i * 128];

    float s = x[0] + x[1] + x[2] + x[3];
    #pragma unroll
    for (int o = 16; o > 0; o >>= 1) s += __shfl_xor_sync(0xffffffffu, s, o);
    if ((tid & 31) == 0) sbuf[tid >> 5] = s;
    __syncthreads();
    float mean = (sbuf[0] + sbuf[1] + sbuf[2] + sbuf[3]) * (1.f / 512.f);
    __syncthreads();

    float q = 0.f;
    #pragma unroll
    for (int i = 0; i < 4; i++) { float d = x[i] - mean; q += d * d; }
    #pragma unroll
    for (int o = 16; o > 0; o >>= 1) q += __shfl_xor_sync(0xffffffffu, q, o);
    if ((tid & 31) == 0) sbuf[tid >> 5] = q;
    __syncthreads();
    float var = (sbuf[0] + sbuf[1] + sbuf[2] + sbuf[3]) * (1.f / 511.f);
    float inv = 1.f / (sqrtf(var) + LN_EPS);

    #pragma unroll
    for (int i = 0; i < 4; i++) {
        int n = tid + i * 128;
        O[base + n] = R[base + n] + ga[n] * (x[i] - mean) * inv + gb[n];
    }
}

// ---------------------------------------------------------------------------
extern "C" void kernel_launch(void* const* d_in, const int* in_sizes, int n_in,
                              void* d_out, int out_size)
{
    const float* img         = (const float*)d_in[0];
    const float* title       = (const float*)d_in[1];
    const int*   mask        = (const int*)  d_in[2];
    const float* scale_img   = (const float*)d_in[3];
    const float* scale_title = (const float*)d_in[4];
    const float* w_proj      = (const float*)d_in[5];
    const float* b_proj      = (const float*)d_in[6];
    const float* w1_img      = (const float*)d_in[7];
    const float* b1_img      = (const float*)d_in[8];
    const float* w2_img      = (const float*)d_in[9];
    const float* b2_img      = (const float*)d_in[10];
    const float* w1_tit      = (const float*)d_in[11];
    const float* b1_tit      = (const float*)d_in[12];
    const float* w2_tit      = (const float*)d_in[13];
    const float* b2_tit      = (const float*)d_in[14];
    const float* ln_a_img    = (const float*)d_in[15];
    const float* ln_b_img    = (const float*)d_in[16];
    const float* ln_a_tit    = (const float*)d_in[17];
    const float* ln_b_tit    = (const float*)d_in[18];

    float* out_img = (float*)d_out;
    float* out_tit = out_img + (size_t)NROW_IMG * DD;

    cudaFuncSetAttribute(gemm_mma, cudaFuncAttributeMaxDynamicSharedMemorySize, SMEM_GEMM);

    __nv_bfloat16 *hid_i_h, *hid_i_l, *hid_t_h, *hid_t_l;
    float *hidp_i, *hidp_t;
    __nv_bfloat16 *hidp_i_h, *hidp_i_l, *hidp_t_h, *hidp_t_l;
    __nv_bfloat16 *ffh_i_h, *ffh_i_l, *ffh_t_h, *ffh_t_l;
    float *ff2_i, *ff2_t;
    __nv_bfloat16 *wp_h, *wp_l, *w1i_h, *w1i_l, *w1t_h, *w1t_l, *w2i_h, *w2i_l, *w2t_h, *w2t_l;

    cudaGetSymbolAddress((void**)&hid_i_h, g_hid_img_h);
    cudaGetSymbolAddress((void**)&hid_i_l, g_hid_img_l);
    cudaGetSymbolAddress((void**)&hid_t_h, g_hid_tit_h);
    cudaGetSymbolAddress((void**)&hid_t_l, g_hid_tit_l);
    cudaGetSymbolAddress((void**)&hidp_i,  g_hidp_img);
    cudaGetSymbolAddress((void**)&hidp_t,  g_hidp_tit);
    cudaGetSymbolAddress((void**)&hidp_i_h, g_hidp_img_h);
    cudaGetSymbolAddress((void**)&hidp_i_l, g_hidp_img_l);
    cudaGetSymbolAddress((void**)&hidp_t_h, g_hidp_tit_h);
    cudaGetSymbolAddress((void**)&hidp_t_l, g_hidp_tit_l);
    cudaGetSymbolAddress((void**)&ffh_i_h, g_ffh_img_h);
    cudaGetSymbolAddress((void**)&ffh_i_l, g_ffh_img_l);
    cudaGetSymbolAddress((void**)&ffh_t_h, g_ffh_tit_h);
    cudaGetSymbolAddress((void**)&ffh_t_l, g_ffh_tit_l);
    cudaGetSymbolAddress((void**)&ff2_i,   g_ff2_img);
    cudaGetSymbolAddress((void**)&ff2_t,   g_ff2_tit);
    cudaGetSymbolAddress((void**)&wp_h,  g_wp_h);  cudaGetSymbolAddress((void**)&wp_l,  g_wp_l);
    cudaGetSymbolAddress((void**)&w1i_h, g_w1i_h); cudaGetSymbolAddress((void**)&w1i_l, g_w1i_l);
    cudaGetSymbolAddress((void**)&w1t_h, g_w1t_h); cudaGetSymbolAddress((void**)&w1t_l, g_w1t_l);
    cudaGetSymbolAddress((void**)&w2i_h, g_w2i_h); cudaGetSymbolAddress((void**)&w2i_l, g_w2i_l);
    cudaGetSymbolAddress((void**)&w2t_h, g_w2t_h); cudaGetSymbolAddress((void**)&w2t_l, g_w2t_l);

    // 0. split weights
    split_kernel<<<(DD*DD)/1024, 256>>>(w_proj, wp_h, wp_l, DD*DD);
    split_kernel<<<(DFF*DD)/1024, 256>>>(w1_img, w1i_h, w1i_l, DFF*DD);
    split_kernel<<<(DFF*DD)/1024, 256>>>(w1_tit, w1t_h, w1t_l, DFF*DD);
    split_kernel<<<(DD*DFF)/1024, 256>>>(w2_img, w2i_h, w2i_l, DD*DFF);
    split_kernel<<<(DD*DFF)/1024, 256>>>(w2_tit, w2t_h, w2t_l, DD*DFF);

    // 1. attention
    attn_kernel<<<BL * HH, 256>>>(img, title, mask, scale_img, scale_title);

    const int MI = NROW_IMG, MT = NROW_TIT;
    int tyi = (MI + 127) / 128, tyt = (MT + 127) / 128;

    // 2. shared projection: f32 + hi/lo
    gemm_mma<<<dim3(DD/128, tyi), 256, SMEM_GEMM>>>(
        hid_i_h, hid_i_l, wp_h, wp_l, b_proj, hidp_i, hidp_i_h, hidp_i_l, MI, DD, DD, 0);
    gemm_mma<<<dim3(DD/128, tyt), 256, SMEM_GEMM>>>(
        hid_t_h, hid_t_l, wp_h, wp_l, b_proj, hidp_t, hidp_t_h, hidp_t_l, MT, DD, DD, 0);

    // 3. FFN1 + gelu: hi/lo only
    gemm_mma<<<dim3(DFF/128, tyi), 256, SMEM_GEMM>>>(
        hidp_i_h, hidp_i_l, w1i_h, w1i_l, b1_img, (float*)0, ffh_i_h, ffh_i_l, MI, DFF, DD, 1);
    gemm_mma<<<dim3(DFF/128, tyt), 256, SMEM_GEMM>>>(
        hidp_t_h, hidp_t_l, w1t_h, w1t_l, b1_tit, (float*)0, ffh_t_h, ffh_t_l, MT, DFF, DD, 1);

    // 4. FFN2: f32 only
    gemm_mma<<<dim3(DD/128, tyi), 256, SMEM_GEMM>>>(
        ffh_i_h, ffh_i_l, w2i_h, w2i_l, b2_img, ff2_i, (__nv_bfloat16*)0, (__nv_bfloat16*)0, MI, DD, DFF, 0);
    gemm_mma<<<dim3(DD/128, tyt), 256, SMEM_GEMM>>>(
        ffh_t_h, ffh_t_l, w2t_h, w2t_l, b2_tit, ff2_t, (__nv_bfloat16*)0, (__nv_bfloat16*)0, MT, DD, DFF, 0);

    // 5. LayerNorm + residual
    ln_res_kernel<<<NROW_IMG, 128>>>(ff2_i, hidp_i, ln_a_img, ln_b_img, out_img);
    ln_res_kernel<<<NROW_TIT, 128>>>(ff2_t, hidp_t, ln_a_tit, ln_b_tit, out_tit);
}

// round 6
// speedup vs baseline: 1.9579x; 1.0486x over previous
#include <cuda_runtime.h>
#include <cuda_bf16.h>
#include <math.h>
#include <stdint.h>

// Problem constants
#define BB 16
#define LL 50
#define PP 49
#define TT 20
#define DD 512
#define HH 8
#define DH 64
#define DFF 2048
#define BL (BB*LL)              // 800
#define NROW_IMG (BL*TT)        // 16000
#define NROW_TIT (BL*PP)        // 39200
#define NROW_ALL (NROW_IMG + NROW_TIT)   // 55200
#define YTILE_IMG (NROW_IMG / 128)       // 125 (exact)
#define NEGV (-1000000000.0f)
#define LN_EPS 1e-6f

// ---------------------------------------------------------------------------
// Scratch (device globals) — img rows first, tit rows after (contiguous)
// ---------------------------------------------------------------------------
__device__ __align__(16) __nv_bfloat16 g_hid_h [(size_t)NROW_ALL * DD];
__device__ __align__(16) __nv_bfloat16 g_hid_l [(size_t)NROW_ALL * DD];
__device__ __align__(16) float         g_hidp_f[(size_t)NROW_ALL * DD];
__device__ __align__(16) __nv_bfloat16 g_hidp_h[(size_t)NROW_ALL * DD];
__device__ __align__(16) __nv_bfloat16 g_hidp_l[(size_t)NROW_ALL * DD];
__device__ __align__(16) __nv_bfloat16 g_ffh_h [(size_t)NROW_ALL * DFF];
__device__ __align__(16) __nv_bfloat16 g_ffh_l [(size_t)NROW_ALL * DFF];
__device__ __align__(16) float         g_ff2   [(size_t)NROW_ALL * DD];
__device__ __align__(16) __nv_bfloat16 g_wp_h [(size_t)DD * DD];
__device__ __align__(16) __nv_bfloat16 g_wp_l [(size_t)DD * DD];
__device__ __align__(16) __nv_bfloat16 g_w1i_h[(size_t)DFF * DD];
__device__ __align__(16) __nv_bfloat16 g_w1i_l[(size_t)DFF * DD];
__device__ __align__(16) __nv_bfloat16 g_w1t_h[(size_t)DFF * DD];
__device__ __align__(16) __nv_bfloat16 g_w1t_l[(size_t)DFF * DD];
__device__ __align__(16) __nv_bfloat16 g_w2i_h[(size_t)DD * DFF];
__device__ __align__(16) __nv_bfloat16 g_w2i_l[(size_t)DD * DFF];
__device__ __align__(16) __nv_bfloat16 g_w2t_h[(size_t)DD * DFF];
__device__ __align__(16) __nv_bfloat16 g_w2t_l[(size_t)DD * DFF];

// ---------------------------------------------------------------------------
// Helpers
// ---------------------------------------------------------------------------
__device__ __forceinline__ uint32_t smem_u32(const void* p) {
    uint32_t a;
    asm("{ .reg .u64 t; cvta.to.shared.u64 t, %1; cvt.u32.u64 %0, t; }" : "=r"(a) : "l"(p));
    return a;
}
__device__ __forceinline__ void cp16(uint32_t dst, const void* src, int sz) {
    asm volatile("cp.async.cg.shared.global [%0], [%1], 16, %2;"
                 :: "r"(dst), "l"(src), "r"(sz));
}
__device__ __forceinline__ void cp_commit() { asm volatile("cp.async.commit_group;" ::: "memory"); }
__device__ __forceinline__ void cp_wait2()  { asm volatile("cp.async.wait_group 2;" ::: "memory"); }
__device__ __forceinline__ void cp_wait1()  { asm volatile("cp.async.wait_group 1;" ::: "memory"); }
__device__ __forceinline__ void cp_wait0()  { asm volatile("cp.async.wait_group 0;" ::: "memory"); }

__device__ __forceinline__ void ldsm4(uint32_t* r, uint32_t addr) {
    asm volatile("ldmatrix.sync.aligned.m8n8.x4.shared.b16 {%0,%1,%2,%3}, [%4];"
                 : "=r"(r[0]), "=r"(r[1]), "=r"(r[2]), "=r"(r[3]) : "r"(addr));
}
__device__ __forceinline__ void mma16816(float* c, const uint32_t* a, const uint32_t* b) {
    asm volatile(
        "mma.sync.aligned.m16n8k16.row.col.f32.bf16.bf16.f32 "
        "{%0,%1,%2,%3}, {%4,%5,%6,%7}, {%8,%9}, {%0,%1,%2,%3};"
        : "+f"(c[0]), "+f"(c[1]), "+f"(c[2]), "+f"(c[3])
        : "r"(a[0]), "r"(a[1]), "r"(a[2]), "r"(a[3]), "r"(b[0]), "r"(b[1]));
}

// gelu_tanh via exact identity tanh(y) = 1 - 2/(1+e^{2y}); inf-safe with intrinsics
__device__ __forceinline__ float gelu_fast(float x) {
    float y = 0.7978845608028654f * (x + 0.044715f * x * x * x);
    float e = __expf(2.f * y);
    return x - __fdividef(x, 1.f + e);
}
__device__ __forceinline__ void split_f32(float v, __nv_bfloat16& h, __nv_bfloat16& l) {
    h = __float2bfloat16(v);
    l = __float2bfloat16(v - __bfloat162float(h));
}

// ---------------------------------------------------------------------------
// Weight split kernel
// ---------------------------------------------------------------------------
__global__ void __launch_bounds__(256) split_kernel(
    const float* __restrict__ x, __nv_bfloat16* __restrict__ hi,
    __nv_bfloat16* __restrict__ lo, int n)
{
    int i = (blockIdx.x * 256 + threadIdx.x) * 4;
    if (i >= n) return;
    float4 v = *(const float4*)(x + i);
    __nv_bfloat16 h0, h1, h2, h3, l0, l1, l2, l3;
    split_f32(v.x, h0, l0); split_f32(v.y, h1, l1);
    split_f32(v.z, h2, l2); split_f32(v.w, h3, l3);
    __nv_bfloat162 hp0 = __halves2bfloat162(h0, h1);
    __nv_bfloat162 hp1 = __halves2bfloat162(h2, h3);
    __nv_bfloat162 lp0 = __halves2bfloat162(l0, l1);
    __nv_bfloat162 lp1 = __halves2bfloat162(l2, l3);
    *(uint2*)(hi + i) = make_uint2(*(uint32_t*)&hp0, *(uint32_t*)&hp1);
    *(uint2*)(lo + i) = make_uint2(*(uint32_t*)&lp0, *(uint32_t*)&lp1);
}

// ---------------------------------------------------------------------------
// Fused attention: one block per (bl, h). Emits bf16 hi/lo into merged layout:
//   img rows:  row = bl*TT + t            (offset 0)
//   tit rows:  row = NROW_IMG + bl*PP + p
// ---------------------------------------------------------------------------
__global__ void __launch_bounds__(256) attn_kernel(
    const float* __restrict__ img, const float* __restrict__ title,
    const int* __restrict__ mask,
    const float* __restrict__ s_img, const float* __restrict__ s_tit)
{
    int blk = blockIdx.x;
    int h   = blk % HH;
    int bl  = blk / HH;

    const float* imgp = img   + (size_t)bl * PP * DD + h * DH;
    const float* titp = title + (size_t)bl * TT * DD + h * DH;
    const int*   mp   = mask  + (size_t)bl * TT;

    __shared__ float sI[PP * DH];
    __shared__ float sT[TT * DH];
    __shared__ float sRaw[PP * TT];
    __shared__ float sPi [PP * TT];
    __shared__ float sPt [TT * PP];
    __shared__ int   sM[TT];

    int tid = threadIdx.x;
    for (int i = tid; i < PP * DH; i += 256) {
        int p = i >> 6, d = i & 63;
        sI[i] = imgp[(size_t)p * DD + d];
    }
    for (int i = tid; i < TT * DH; i += 256) {
        int t = i >> 6, d = i & 63;
        sT[i] = titp[(size_t)t * DD + d];
    }
    if (tid < TT) sM[tid] = mp[tid];
    __syncthreads();

    for (int i = tid; i < PP * TT; i += 256) {
        int p = i / TT, t = i % TT;
        const float* ip = &sI[p * DH];
        const float* tp = &sT[t * DH];
        float acc = 0.f;
        #pragma unroll
        for (int d = 0; d < DH; d++) acc += ip[d] * tp[d];
        sRaw[i] = acc * 0.125f;
    }
    __syncthreads();

    if (tid < PP) {
        int p = tid;
        float sc = s_img[h * PP + p];
        float mx = -1e30f;
        for (int t = 0; t < TT; t++) {
            float x = (sM[t] == 0) ? NEGV : sRaw[p * TT + t] * sc;
            sPi[p * TT + t] = x;
            mx = fmaxf(mx, x);
        }
        float sum = 0.f;
        for (int t = 0; t < TT; t++) {
            float e = __expf(sPi[p * TT + t] - mx);
            sPi[p * TT + t] = e;
            sum += e;
        }
        float inv = 1.f / sum;
        for (int t = 0; t < TT; t++) sPi[p * TT + t] *= inv;
    }
    if (tid >= 64 && tid < 64 + TT) {
        int t = tid - 64;
        float sc = s_tit[h * TT + t];
        bool m0 = (sM[t] == 0);
        float mx = -1e30f;
        for (int p = 0; p < PP; p++) {
            float x = m0 ? NEGV : sRaw[p * TT + t] * sc;
            sPt[t * PP + p] = x;
            mx = fmaxf(mx, x);
        }
        float sum = 0.f;
        for (int p = 0; p < PP; p++) {
            float e = __expf(sPt[t * PP + p] - mx);
            sPt[t * PP + p] = e;
            sum += e;
        }
        float inv = 1.f / sum;
        for (int p = 0; p < PP; p++) sPt[t * PP + p] *= inv;
    }
    __syncthreads();

    // tit rows
    for (int i = tid; i < PP * DH; i += 256) {
        int p = i >> 6, d = i & 63;
        float acc = 0.f;
        #pragma unroll
        for (int t = 0; t < TT; t++) acc += sPi[p * TT + t] * sT[t * DH + d];
        size_t idx = ((size_t)(NROW_IMG + bl * PP + p)) * DD + h * DH + d;
        __nv_bfloat16 hh, ll;
        split_f32(acc, hh, ll);
        g_hid_h[idx] = hh;
        g_hid_l[idx] = ll;
    }
    // img rows
    for (int i = tid; i < TT * DH; i += 256) {
        int t = i >> 6, d = i & 63;
        float acc = 0.f;
        #pragma unroll
        for (int p = 0; p < PP; p++) acc += sPt[t * PP + p] * sI[p * DH + d];
        size_t idx = ((size_t)(bl * TT + t)) * DD + h * DH + d;
        __nv_bfloat16 hh, ll;
        split_f32(acc, hh, ll);
        g_hid_h[idx] = hh;
        g_hid_l[idx] = ll;
    }
}

// ---------------------------------------------------------------------------
// mma.sync GEMM (bf16x3): C[M,N] = act(A @ W^T + bias)
// Block tile 128x128, 8 warps (32m x 64n each), KC=32, 4-stage cp.async,
// one __syncthreads per K-chunk. Weights selected per row-region (ysplit).
// ---------------------------------------------------------------------------
#define KC 32
#define PSTRIDE 40
#define TEN_BYTES (128 * PSTRIDE * 2)    // 10240
#define STG_BYTES (4 * TEN_BYTES)        // 40960
#define NSTAGE 4
#define SMEM_GEMM (NSTAGE * STG_BYTES)   // 163840

__device__ __forceinline__ void load_stage(
    uint32_t st,
    const __nv_bfloat16* __restrict__ Ah, const __nv_bfloat16* __restrict__ Al,
    const __nv_bfloat16* __restrict__ Wh, const __nv_bfloat16* __restrict__ Wl,
    int m0, int n0, int M, int K, int k0, int tid)
{
    #pragma unroll
    for (int i = 0; i < 2; i++) {
        int c = tid + i * 256;            // 0..511
        int row = c >> 2, kseg = c & 3;   // row<128, 16B segment
        uint32_t doff = (uint32_t)(row * (PSTRIDE * 2) + kseg * 16);
        int ar = m0 + row;
        int ok = (ar < M);
        size_t ao = (size_t)(ok ? ar : 0) * K + k0 + kseg * 8;
        cp16(st + doff,                 Ah + ao, ok ? 16 : 0);
        cp16(st + TEN_BYTES + doff,     Al + ao, ok ? 16 : 0);
        size_t wo = (size_t)(n0 + row) * K + k0 + kseg * 8;
        cp16(st + 2 * TEN_BYTES + doff, Wh + wo, 16);
        cp16(st + 3 * TEN_BYTES + doff, Wl + wo, 16);
    }
}

__global__ void __launch_bounds__(256) gemm_mma(
    const __nv_bfloat16* __restrict__ Ah, const __nv_bfloat16* __restrict__ Al,
    const __nv_bfloat16* __restrict__ WhA, const __nv_bfloat16* __restrict__ WlA,
    const __nv_bfloat16* __restrict__ WhB, const __nv_bfloat16* __restrict__ WlB,
    const float* __restrict__ biasA, const float* __restrict__ biasB,
    float* __restrict__ Cf, __nv_bfloat16* __restrict__ Chi, __nv_bfloat16* __restrict__ Clo,
    int M, int N, int K, int act, int ysplit)
{
    extern __shared__ __align__(16) char smem[];
    uint32_t sb = smem_u32(smem);
    int tid  = threadIdx.x;
    int wid  = tid >> 5, lane = tid & 31;
    int m0   = blockIdx.y * 128;
    int n0   = blockIdx.x * 128;
    int wm   = (wid & 3) * 32;
    int wn   = (wid >> 2) * 64;

    bool regA = ((int)blockIdx.y < ysplit);
    const __nv_bfloat16* Wh = regA ? WhA : WhB;
    const __nv_bfloat16* Wl = regA ? WlA : WlB;
    const float*       bias = regA ? biasA : biasB;

    float acc[2][8][4];
    #pragma unroll
    for (int a = 0; a < 2; a++)
        #pragma unroll
        for (int b = 0; b < 8; b++)
            #pragma unroll
            for (int c = 0; c < 4; c++) acc[a][b][c] = 0.f;

    int nk = K / KC;
    load_stage(sb,                 Ah, Al, Wh, Wl, m0, n0, M, K, 0,      tid); cp_commit();
    load_stage(sb + STG_BYTES,     Ah, Al, Wh, Wl, m0, n0, M, K, KC,     tid); cp_commit();
    load_stage(sb + 2 * STG_BYTES, Ah, Al, Wh, Wl, m0, n0, M, K, 2 * KC, tid); cp_commit();

    uint32_t a_row = (uint32_t)(lane & 15);
    uint32_t a_kof = (uint32_t)((lane >> 4) << 3);
    uint32_t b_r8  = (uint32_t)(lane & 7);
    uint32_t b_kof = (uint32_t)(((lane >> 3) & 1) << 3);
    uint32_t b_pr  = (uint32_t)(lane >> 4);

    for (int it = 0; it < nk; it++) {
        if (it <= nk - 3)      cp_wait2();
        else if (it == nk - 2) cp_wait1();
        else                   cp_wait0();
        __syncthreads();
        if (it + 3 < nk) {
            load_stage(sb + (uint32_t)((it + 3) & 3) * STG_BYTES,
                       Ah, Al, Wh, Wl, m0, n0, M, K, (it + 3) * KC, tid);
            cp_commit();
        }
        uint32_t st = sb + (uint32_t)(it & 3) * STG_BYTES;

        #pragma unroll
        for (int kk = 0; kk < KC; kk += 16) {
            uint32_t ah[2][4], al[2][4], bh[8][2], blr[8][2];
            #pragma unroll
            for (int mt = 0; mt < 2; mt++) {
                uint32_t r = (uint32_t)(wm + mt * 16) + a_row;
                uint32_t ad = st + r * (PSTRIDE * 2) + ((uint32_t)kk + a_kof) * 2;
                ldsm4(ah[mt], ad);
                ldsm4(al[mt], ad + TEN_BYTES);
            }
            #pragma unroll
            for (int np = 0; np < 4; np++) {
                uint32_t rr = (uint32_t)wn + ((uint32_t)np * 2 + b_pr) * 8 + b_r8;
                uint32_t bd = st + 2 * TEN_BYTES + rr * (PSTRIDE * 2) + ((uint32_t)kk + b_kof) * 2;
                uint32_t t0[4], t1[4];
                ldsm4(t0, bd);
                ldsm4(t1, bd + TEN_BYTES);
                bh [np*2][0]   = t0[0]; bh [np*2][1]   = t0[1];
                bh [np*2+1][0] = t0[2]; bh [np*2+1][1] = t0[3];
                blr[np*2][0]   = t1[0]; blr[np*2][1]   = t1[1];
                blr[np*2+1][0] = t1[2]; blr[np*2+1][1] = t1[3];
            }
            #pragma unroll
            for (int mt = 0; mt < 2; mt++)
                #pragma unroll
                for (int nt = 0; nt < 8; nt++) {
                    mma16816(acc[mt][nt], ah[mt], bh[nt]);
                    mma16816(acc[mt][nt], ah[mt], blr[nt]);
                    mma16816(acc[mt][nt], al[mt], bh[nt]);
                }
        }
    }

    // epilogue
    int gr = lane >> 2;
    int gc = (lane & 3) * 2;
    #pragma unroll
    for (int mt = 0; mt < 2; mt++) {
        int m_lo = m0 + wm + mt * 16 + gr;
        int m_hi = m_lo + 8;
        #pragma unroll
        for (int nt = 0; nt < 8; nt++) {
            int n = n0 + wn + nt * 8 + gc;
            float2 bv = *(const float2*)&bias[n];
            float v0 = acc[mt][nt][0] + bv.x;
            float v1 = acc[mt][nt][1] + bv.y;
            float v2 = acc[mt][nt][2] + bv.x;
            float v3 = acc[mt][nt][3] + bv.y;
            if (act) { v0 = gelu_fast(v0); v1 = gelu_fast(v1);
                       v2 = gelu_fast(v2); v3 = gelu_fast(v3); }
            if (m_lo < M) {
                size_t o = (size_t)m_lo * N + n;
                if (Cf) *(float2*)&Cf[o] = make_float2(v0, v1);
                if (Chi) {
                    __nv_bfloat16 h0, l0, h1, l1;
                    split_f32(v0, h0, l0); split_f32(v1, h1, l1);
                    __nv_bfloat162 hp = __halves2bfloat162(h0, h1);
                    __nv_bfloat162 lp = __halves2bfloat162(l0, l1);
                    *(uint32_t*)&Chi[o] = *(uint32_t*)&hp;
                    *(uint32_t*)&Clo[o] = *(uint32_t*)&lp;
                }
            }
            if (m_hi < M) {
                size_t o = (size_t)m_hi * N + n;
                if (Cf) *(float2*)&Cf[o] = make_float2(v2, v3);
                if (Chi) {
                    __nv_bfloat16 h0, l0, h1, l1;
                    split_f32(v2, h0, l0); split_f32(v3, h1, l1);
                    __nv_bfloat162 hp = __halves2bfloat162(h0, h1);
                    __nv_bfloat162 lp = __halves2bfloat162(l0, l1);
                    *(uint32_t*)&Chi[o] = *(uint32_t*)&hp;
                    *(uint32_t*)&Clo[o] = *(uint32_t*)&lp;
                }
            }
        }
    }
}

// ---------------------------------------------------------------------------
// out = R + a * (Y - mean) / (std + eps) + b   per row of 512, ddof=1
// region-selected ga/gb (img rows first)
// ---------------------------------------------------------------------------
__global__ void __launch_bounds__(128) ln_res_kernel(
    const float* __restrict__ Y, const float* __restrict__ R,
    const float* __restrict__ ga_i, const float* __restrict__ gb_i,
    const float* __restrict__ ga_t, const float* __restrict__ gb_t,
    float* __restrict__ O)
{
    __shared__ float sbuf[4];
    int row = blockIdx.x;
    const float* ga = (row < NROW_IMG) ? ga_i : ga_t;
    const float* gb = (row < NROW_IMG) ? gb_i : gb_t;
    size_t base = (size_t)row * DD;
    int tid = threadIdx.x;

    float x[4];
    #pragma unroll
    for (int i = 0; i < 4; i++) x[i] = Y[base + tid + i * 128];

    float s = x[0] + x[1] + x[2] + x[3];
    #pragma unroll
    for (int o = 16; o > 0; o >>= 1) s += __shfl_xor_sync(0xffffffffu, s, o);
    if ((tid & 31) == 0) sbuf[tid >> 5] = s;
    __syncthreads();
    float mean = (sbuf[0] + sbuf[1] + sbuf[2] + sbuf[3]) * (1.f / 512.f);
    __syncthreads();

    float q = 0.f;
    #pragma unroll
    for (int i = 0; i < 4; i++) { float d = x[i] - mean; q += d * d; }
    #pragma unroll
    for (int o = 16; o > 0; o >>= 1) q += __shfl_xor_sync(0xffffffffu, q, o);
    if ((tid & 31) == 0) sbuf[tid >> 5] = q;
    __syncthreads();
    float var = (sbuf[0] + sbuf[1] + sbuf[2] + sbuf[3]) * (1.f / 511.f);
    float inv = 1.f / (sqrtf(var) + LN_EPS);

    #pragma unroll
    for (int i = 0; i < 4; i++) {
        int n = tid + i * 128;
        O[base + n] = R[base + n] + ga[n] * (x[i] - mean) * inv + gb[n];
    }
}

// ---------------------------------------------------------------------------
extern "C" void kernel_launch(void* const* d_in, const int* in_sizes, int n_in,
                              void* d_out, int out_size)
{
    const float* img         = (const float*)d_in[0];
    const float* title       = (const float*)d_in[1];
    const int*   mask        = (const int*)  d_in[2];
    const float* scale_img   = (const float*)d_in[3];
    const float* scale_title = (const float*)d_in[4];
    const float* w_proj      = (const float*)d_in[5];
    const float* b_proj      = (const float*)d_in[6];
    const float* w1_img      = (const float*)d_in[7];
    const float* b1_img      = (const float*)d_in[8];
    const float* w2_img      = (const float*)d_in[9];
    const float* b2_img      = (const float*)d_in[10];
    const float* w1_tit      = (const float*)d_in[11];
    const float* b1_tit      = (const float*)d_in[12];
    const float* w2_tit      = (const float*)d_in[13];
    const float* b2_tit      = (const float*)d_in[14];
    const float* ln_a_img    = (const float*)d_in[15];
    const float* ln_b_img    = (const float*)d_in[16];
    const float* ln_a_tit    = (const float*)d_in[17];
    const float* ln_b_tit    = (const float*)d_in[18];

    float* out = (float*)d_out;   // img rows then tit rows (contiguous)

    cudaFuncSetAttribute(gemm_mma, cudaFuncAttributeMaxDynamicSharedMemorySize, SMEM_GEMM);

    __nv_bfloat16 *hid_h, *hid_l, *hidp_h, *hidp_l, *ffh_h, *ffh_l;
    float *hidp_f, *ff2;
    __nv_bfloat16 *wp_h, *wp_l, *w1i_h, *w1i_l, *w1t_h, *w1t_l, *w2i_h, *w2i_l, *w2t_h, *w2t_l;

    cudaGetSymbolAddress((void**)&hid_h,  g_hid_h);
    cudaGetSymbolAddress((void**)&hid_l,  g_hid_l);
    cudaGetSymbolAddress((void**)&hidp_f, g_hidp_f);
    cudaGetSymbolAddress((void**)&hidp_h, g_hidp_h);
    cudaGetSymbolAddress((void**)&hidp_l, g_hidp_l);
    cudaGetSymbolAddress((void**)&ffh_h,  g_ffh_h);
    cudaGetSymbolAddress((void**)&ffh_l,  g_ffh_l);
    cudaGetSymbolAddress((void**)&ff2,    g_ff2);
    cudaGetSymbolAddress((void**)&wp_h,  g_wp_h);  cudaGetSymbolAddress((void**)&wp_l,  g_wp_l);
    cudaGetSymbolAddress((void**)&w1i_h, g_w1i_h); cudaGetSymbolAddress((void**)&w1i_l, g_w1i_l);
    cudaGetSymbolAddress((void**)&w1t_h, g_w1t_h); cudaGetSymbolAddress((void**)&w1t_l, g_w1t_l);
    cudaGetSymbolAddress((void**)&w2i_h, g_w2i_h); cudaGetSymbolAddress((void**)&w2i_l, g_w2i_l);
    cudaGetSymbolAddress((void**)&w2t_h, g_w2t_h); cudaGetSymbolAddress((void**)&w2t_l, g_w2t_l);

    // 0. split weights
    split_kernel<<<(DD*DD)/1024, 256>>>(w_proj, wp_h, wp_l, DD*DD);
    split_kernel<<<(DFF*DD)/1024, 256>>>(w1_img, w1i_h, w1i_l, DFF*DD);
    split_kernel<<<(DFF*DD)/1024, 256>>>(w1_tit, w1t_h, w1t_l, DFF*DD);
    split_kernel<<<(DD*DFF)/1024, 256>>>(w2_img, w2i_h, w2i_l, DD*DFF);
    split_kernel<<<(DD*DFF)/1024, 256>>>(w2_tit, w2t_h, w2t_l, DD*DFF);

    // 1. attention
    attn_kernel<<<BL * HH, 256>>>(img, title, mask, scale_img, scale_title);

    int ty = (NROW_ALL + 127) / 128;   // 432

    // 2. shared projection (same weights both regions)
    gemm_mma<<<dim3(DD/128, ty), 256, SMEM_GEMM>>>(
        hid_h, hid_l, wp_h, wp_l, wp_h, wp_l, b_proj, b_proj,
        hidp_f, hidp_h, hidp_l, NROW_ALL, DD, DD, 0, ty);

    // 3. FFN1 + gelu (region-split weights)
    gemm_mma<<<dim3(DFF/128, ty), 256, SMEM_GEMM>>>(
        hidp_h, hidp_l, w1i_h, w1i_l, w1t_h, w1t_l, b1_img, b1_tit,
        (float*)0, ffh_h, ffh_l, NROW_ALL, DFF, DD, 1, YTILE_IMG);

    // 4. FFN2 (region-split weights)
    gemm_mma<<<dim3(DD/128, ty), 256, SMEM_GEMM>>>(
        ffh_h, ffh_l, w2i_h, w2i_l, w2t_h, w2t_l, b2_img, b2_tit,
        ff2, (__nv_bfloat16*)0, (__nv_bfloat16*)0, NROW_ALL, DD, DFF, 0, YTILE_IMG);

    // 5. LayerNorm + residual (merged)
    ln_res_kernel<<<NROW_ALL, 128>>>(ff2, hidp_f, ln_a_img, ln_b_img, ln_a_tit, ln_b_tit, out);
}